// round 7
// baseline (speedup 1.0000x reference)
#include <cuda_runtime.h>
#include <cstdint>

// REWAEncoder: out = (FWHT_128(x @ W^T)/sqrt(128) > 0)
// R7: mma.sync m16n8k8 split-TF32 (3 passes, fp32 accum) + FWHT + sign.
// Rows with min|h| < TAU are flagged and recomputed bit-exactly with the
// reference's sequential fp32 fma chain (rel_err 0.0 verified in R2).
//
// x [32768,1024] f32, W [128,1024] f32, out [32768,128] f32.

#define K_DIM 1024
#define MOUT  128
#define NROWS 32768
#define TAU   2e-4f
#define KP    20          // smem k-pitch (floats) for 16-wide k-chunks

__device__ __align__(16) uint32_t g_Whi[MOUT * K_DIM];
__device__ __align__(16) uint32_t g_Wlo[MOUT * K_DIM];
__device__ int g_flags[NROWS];

// smem float offsets (dynamic smem, 15360 floats = 61440 B)
#define SM_AHI 0
#define SM_ALO 2560
#define SM_B0H 5120
#define SM_B0L 7680
#define SM_B1H 10240
#define SM_B1L 12800
#define SM_FLOATS 15360

__device__ __forceinline__ uint32_t f2tf32(float f) {
    uint32_t r;
    asm("cvt.rna.tf32.f32 %0, %1;" : "=r"(r) : "f"(f));
    return r;
}

__device__ __forceinline__ void mma_tf32(float* c, const uint32_t* a, const uint32_t* b) {
    asm volatile(
        "mma.sync.aligned.m16n8k8.row.col.f32.tf32.tf32.f32 "
        "{%0,%1,%2,%3}, {%4,%5,%6,%7}, {%8,%9}, {%0,%1,%2,%3};"
        : "+f"(c[0]), "+f"(c[1]), "+f"(c[2]), "+f"(c[3])
        : "r"(a[0]), "r"(a[1]), "r"(a[2]), "r"(a[3]), "r"(b[0]), "r"(b[1]));
}

__device__ __forceinline__ uint32_t smem_u32(const void* p) {
    uint32_t a;
    asm("{ .reg .u64 t; cvta.to.shared.u64 t, %1; cvt.u32.u64 %0, t; }"
        : "=r"(a) : "l"(p));
    return a;
}

__device__ __forceinline__ void cp_async16(uint32_t dst, const void* src) {
    asm volatile("cp.async.ca.shared.global [%0], [%1], 16;"
                 :: "r"(dst), "l"(src) : "memory");
}

// ---------------- prep: split W into tf32 hi/lo ----------------
__global__ void split_w_kernel(const float* __restrict__ W) {
    const int i = blockIdx.x * blockDim.x + threadIdx.x;
    const float w = W[i];
    const uint32_t hi = f2tf32(w);
    g_Whi[i] = hi;
    g_Wlo[i] = f2tf32(w - __uint_as_float(hi));
}

// ---------------- main: split-TF32 mma GEMM + FWHT + sign + flag ----------
__global__ void __launch_bounds__(256, 2)
tensor_gemm_kernel(const float* __restrict__ x, float* __restrict__ out) {
    extern __shared__ __align__(16) float sm[];
    const uint32_t sb = smem_u32(sm);

    const int tid  = threadIdx.x;
    const int wid  = tid >> 5;
    const int lane = tid & 31;
    const int tg   = lane & 3;        // thread-in-group (k)
    const int g    = lane >> 2;       // group (row/col)
    const int warpM = wid & 3;        // 0..3 -> M rows warpM*32
    const int warpN = wid >> 2;       // 0..1 -> N cols warpN*64
    const int block_row = blockIdx.x * 128;

    // staging map: thread -> (row 0..127, k-half 0/8)
    const int srow = tid >> 1;
    const int kh   = (tid & 1) * 8;
    const float* xrow = x + (size_t)(block_row + srow) * K_DIM + kh;
    const uint32_t* whrow = g_Whi + (size_t)srow * K_DIM + kh;
    const uint32_t* wlrow = g_Wlo + (size_t)srow * K_DIM + kh;

    const uint32_t b_base[2][2] = {{sb + SM_B0H * 4, sb + SM_B0L * 4},
                                   {sb + SM_B1H * 4, sb + SM_B1L * 4}};

    float acc[2][8][4];
#pragma unroll
    for (int mi = 0; mi < 2; ++mi)
#pragma unroll
        for (int ni = 0; ni < 8; ++ni)
#pragma unroll
            for (int r = 0; r < 4; ++r) acc[mi][ni][r] = 0.0f;

    // prologue: W chunk0 -> buf0 (async), x chunk0 -> regs
    {
        const uint32_t soff = (srow * KP + kh) * 4;
        cp_async16(b_base[0][0] + soff, whrow);
        cp_async16(b_base[0][0] + soff + 16, whrow + 4);
        cp_async16(b_base[0][1] + soff, wlrow);
        cp_async16(b_base[0][1] + soff + 16, wlrow + 4);
        asm volatile("cp.async.commit_group;" ::: "memory");
    }
    float4 px0 = *(const float4*)(xrow);
    float4 px1 = *(const float4*)(xrow + 4);

    for (int c = 0; c < 64; ++c) {
        const int buf = c & 1;
        __syncthreads();    // prior chunk's tile reads complete

        // convert + store x chunk c (tf32 hi/lo bit patterns stored as floats)
        {
            uint4 hi, lo;
            float* Ah = sm + SM_AHI + srow * KP + kh;
            float* Al = sm + SM_ALO + srow * KP + kh;
            hi.x = f2tf32(px0.x); lo.x = f2tf32(px0.x - __uint_as_float(hi.x));
            hi.y = f2tf32(px0.y); lo.y = f2tf32(px0.y - __uint_as_float(hi.y));
            hi.z = f2tf32(px0.z); lo.z = f2tf32(px0.z - __uint_as_float(hi.z));
            hi.w = f2tf32(px0.w); lo.w = f2tf32(px0.w - __uint_as_float(hi.w));
            *(uint4*)(Ah) = hi; *(uint4*)(Al) = lo;
            hi.x = f2tf32(px1.x); lo.x = f2tf32(px1.x - __uint_as_float(hi.x));
            hi.y = f2tf32(px1.y); lo.y = f2tf32(px1.y - __uint_as_float(hi.y));
            hi.z = f2tf32(px1.z); lo.z = f2tf32(px1.z - __uint_as_float(hi.z));
            hi.w = f2tf32(px1.w); lo.w = f2tf32(px1.w - __uint_as_float(hi.w));
            *(uint4*)(Ah + 4) = hi; *(uint4*)(Al + 4) = lo;
        }

        // issue W for chunk c+1 into the other buffer; prefetch x c+1
        if (c + 1 < 64) {
            const uint32_t soff = (srow * KP + kh) * 4;
            const int nb = (c + 1) & 1;
            cp_async16(b_base[nb][0] + soff, whrow + (c + 1) * 16);
            cp_async16(b_base[nb][0] + soff + 16, whrow + (c + 1) * 16 + 4);
            cp_async16(b_base[nb][1] + soff, wlrow + (c + 1) * 16);
            cp_async16(b_base[nb][1] + soff + 16, wlrow + (c + 1) * 16 + 4);
            asm volatile("cp.async.commit_group;" ::: "memory");
            asm volatile("cp.async.wait_group 1;" ::: "memory");  // chunk c arrived
            px0 = *(const float4*)(xrow + (c + 1) * 16);
            px1 = *(const float4*)(xrow + (c + 1) * 16 + 4);
        } else {
            asm volatile("cp.async.wait_group 0;" ::: "memory");
        }
        __syncthreads();

        // compute: 2 k-steps of 8
        const float* Ah = sm + SM_AHI;
        const float* Al = sm + SM_ALO;
        const float* Bh = sm + (buf ? SM_B1H : SM_B0H);
        const float* Bl = sm + (buf ? SM_B1L : SM_B0L);
#pragma unroll
        for (int s = 0; s < 2; ++s) {
            const int kb = s * 8 + tg;
            uint32_t ah[2][4], bb[8][2];
#pragma unroll
            for (int mi = 0; mi < 2; ++mi) {
                const int rb = (warpM * 32 + mi * 16 + g) * KP;
                ah[mi][0] = __float_as_uint(Ah[rb + kb]);
                ah[mi][1] = __float_as_uint(Ah[rb + 8 * KP + kb]);
                ah[mi][2] = __float_as_uint(Ah[rb + kb + 4]);
                ah[mi][3] = __float_as_uint(Ah[rb + 8 * KP + kb + 4]);
            }
#pragma unroll
            for (int ni = 0; ni < 8; ++ni) {
                const int nb = (warpN * 64 + ni * 8 + g) * KP;
                bb[ni][0] = __float_as_uint(Bh[nb + kb]);
                bb[ni][1] = __float_as_uint(Bh[nb + kb + 4]);
            }
            // hi*hi
#pragma unroll
            for (int mi = 0; mi < 2; ++mi)
#pragma unroll
                for (int ni = 0; ni < 8; ++ni) mma_tf32(acc[mi][ni], ah[mi], bb[ni]);
            // lo*hi
#pragma unroll
            for (int mi = 0; mi < 2; ++mi) {
                uint32_t al[4];
                const int rb = (warpM * 32 + mi * 16 + g) * KP;
                al[0] = __float_as_uint(Al[rb + kb]);
                al[1] = __float_as_uint(Al[rb + 8 * KP + kb]);
                al[2] = __float_as_uint(Al[rb + kb + 4]);
                al[3] = __float_as_uint(Al[rb + 8 * KP + kb + 4]);
#pragma unroll
                for (int ni = 0; ni < 8; ++ni) mma_tf32(acc[mi][ni], al, bb[ni]);
            }
            // hi*lo
#pragma unroll
            for (int ni = 0; ni < 8; ++ni) {
                const int nb = (warpN * 64 + ni * 8 + g) * KP;
                bb[ni][0] = __float_as_uint(Bl[nb + kb]);
                bb[ni][1] = __float_as_uint(Bl[nb + kb + 4]);
            }
#pragma unroll
            for (int mi = 0; mi < 2; ++mi)
#pragma unroll
                for (int ni = 0; ni < 8; ++ni) mma_tf32(acc[mi][ni], ah[mi], bb[ni]);
        }
    }
    __syncthreads();

    // ---- epilogue: FWHT (reference order, fp32) + sign + flag, 64 rows/phase ----
    float (*hb)[132] = reinterpret_cast<float(*)[132]>(sm);
    const float scale = 0.08838834764831844f;   // fp32(1/sqrt(128))

    for (int hs = 0; hs < 2; ++hs) {
        if ((warpM >> 1) == hs) {
            const int lr0 = (warpM & 1) * 32;
#pragma unroll
            for (int mi = 0; mi < 2; ++mi)
#pragma unroll
                for (int ni = 0; ni < 8; ++ni)
#pragma unroll
                    for (int r = 0; r < 4; ++r) {
                        const int lr = lr0 + mi * 16 + g + 8 * (r >> 1);
                        const int cc = warpN * 64 + ni * 8 + tg * 2 + (r & 1);
                        hb[lr][cc] = acc[mi][ni][r];
                    }
        }
        __syncthreads();

        for (int half = 1; half < MOUT; half <<= 1) {
#pragma unroll
            for (int p = 0; p < 16; ++p) {          // 64*64 pairs / 256 thr
                const int pidx = tid + p * 256;
                const int row = pidx >> 6;
                const int t   = pidx & 63;
                const int j   = ((t & ~(half - 1)) << 1) | (t & (half - 1));
                const float a = hb[row][j];
                const float b = hb[row][j + half];
                hb[row][j]        = a + b;
                hb[row][j + half] = a - b;
            }
            __syncthreads();
        }

        // sign + store + fragility flag: 4 threads per row, 32 cols each
        const int r  = tid >> 2;
        const int cb = (tid & 3) * 32;
        float mn = 1e30f;
#pragma unroll
        for (int cc = 0; cc < 32; cc += 4) {
            const float4 v = *(const float4*)&hb[r][cb + cc];
            const float s0 = v.x * scale, s1 = v.y * scale,
                        s2 = v.z * scale, s3 = v.w * scale;
            float4 o;
            o.x = s0 > 0.0f ? 1.0f : 0.0f;
            o.y = s1 > 0.0f ? 1.0f : 0.0f;
            o.z = s2 > 0.0f ? 1.0f : 0.0f;
            o.w = s3 > 0.0f ? 1.0f : 0.0f;
            mn = fminf(mn, fminf(fminf(fabsf(s0), fabsf(s1)),
                                 fminf(fabsf(s2), fabsf(s3))));
            *(float4*)(out + (size_t)(block_row + hs * 64 + r) * MOUT + cb + cc) = o;
        }
        mn = fminf(mn, __shfl_xor_sync(0xffffffffu, mn, 1));
        mn = fminf(mn, __shfl_xor_sync(0xffffffffu, mn, 2));
        if ((tid & 3) == 0) g_flags[block_row + hs * 64 + r] = (mn < TAU) ? 1 : 0;
        __syncthreads();
    }
}

// ---------------- exact fix: one block per row, bit-exact reference chain ----
__global__ void __launch_bounds__(128)
fix_rows_kernel(const float* __restrict__ x, const float* __restrict__ W,
                float* __restrict__ out) {
    const int row = blockIdx.x;
    if (!g_flags[row]) return;

    __shared__ float xs[K_DIM];
    __shared__ float hrow[MOUT];
    const int t = threadIdx.x;     // 0..127

    for (int cc = t; cc < K_DIM / 4; cc += 128)
        *(float4*)&xs[cc * 4] = *(const float4*)&x[(size_t)row * K_DIM + cc * 4];
    __syncthreads();

    float acc = 0.0f;
    const float* wr = W + (size_t)t * K_DIM;
    for (int d = 0; d < K_DIM; ++d)
        acc = fmaf(xs[d], wr[d], acc);
    hrow[t] = acc;
    __syncthreads();

    for (int half = 1; half < MOUT; half <<= 1) {
        if (t < MOUT / 2) {
            const int j = ((t & ~(half - 1)) << 1) | (t & (half - 1));
            const float a = hrow[j];
            const float b = hrow[j + half];
            hrow[j]        = a + b;
            hrow[j + half] = a - b;
        }
        __syncthreads();
    }
    out[(size_t)row * MOUT + t] =
        (hrow[t] * 0.08838834764831844f > 0.0f) ? 1.0f : 0.0f;
}

// ---------------- launch ----------------
extern "C" void kernel_launch(void* const* d_in, const int* in_sizes, int n_in,
                              void* d_out, int out_size) {
    const float* x = (const float*)d_in[0];   // [32768, 1024]
    const float* W = (const float*)d_in[1];   // [128, 1024]
    float* out = (float*)d_out;               // [32768, 128]

    cudaFuncSetAttribute(tensor_gemm_kernel,
                         cudaFuncAttributeMaxDynamicSharedMemorySize,
                         SM_FLOATS * 4);

    split_w_kernel<<<(MOUT * K_DIM) / 256, 256>>>(W);
    tensor_gemm_kernel<<<NROWS / 128, 256, SM_FLOATS * 4>>>(x, out);
    fix_rows_kernel<<<NROWS, 128>>>(x, W, out);
}